// round 1
// baseline (speedup 1.0000x reference)
#include <cuda_runtime.h>

// Problem constants (from reference)
#define NN 64
#define CC 256
#define HH 56
#define WW 56
#define EMBED 16
#define INDEX_K 16              // ceil(256^0.5) = 16
#define HW (HH * WW)            // 3136
#define HW4 (HW / 4)            // 784 float4 per (n,c) slab
#define SCALE (256.0f / 240.0f) // c / (c - INDEX)

// Per-(n,c) multiplier scratch: keep * scale (0 or 256/240)
__device__ float g_mult[NN * CC];

// Kernel 1: compute activ = embeds @ table, rank per row, write multiplier.
// Grid: NN blocks, CC threads. Thread c handles channel c of sample blockIdx.x.
__global__ void mask_kernel(const float* __restrict__ embeds,
                            const float* __restrict__ table) {
    __shared__ float s_act[CC];
    __shared__ float s_emb[EMBED];
    const int n = blockIdx.x;
    const int c = threadIdx.x;

    if (c < EMBED) s_emb[c] = embeds[n * EMBED + c];
    __syncthreads();

    // activ[n][c] = sum_e embeds[n][e] * table[e][c]
    float a = 0.0f;
#pragma unroll
    for (int e = 0; e < EMBED; ++e) {
        a += s_emb[e] * table[e * CC + c];
    }
    s_act[c] = a;
    __syncthreads();

    // count of values <= a  (sorted[INDEX] <= a  <=>  at least INDEX+1 values <= a)
    int cnt = 0;
#pragma unroll 8
    for (int j = 0; j < CC; ++j) {
        cnt += (s_act[j] <= a) ? 1 : 0;
    }
    g_mult[n * CC + c] = (cnt >= INDEX_K + 1) ? SCALE : 0.0f;
}

// Kernel 2: out = x * mult[n][c], vectorized float4.
// Grid: NN*CC blocks; each block owns one contiguous HW slab (784 float4).
__global__ void __launch_bounds__(256) scale_kernel(const float4* __restrict__ x,
                                                    float4* __restrict__ out) {
    const int nc = blockIdx.x;
    const float m = g_mult[nc];
    const long long base = (long long)nc * HW4;
    const float4* __restrict__ xin = x + base;
    float4* __restrict__ o = out + base;

    // 784 = 3*256 + 16
    int t = threadIdx.x;
#pragma unroll
    for (int it = 0; it < 3; ++it) {
        float4 v = xin[t];
        v.x *= m; v.y *= m; v.z *= m; v.w *= m;
        o[t] = v;
        t += 256;
    }
    if (t < HW4) {
        float4 v = xin[t];
        v.x *= m; v.y *= m; v.z *= m; v.w *= m;
        o[t] = v;
    }
}

extern "C" void kernel_launch(void* const* d_in, const int* in_sizes, int n_in,
                              void* d_out, int out_size) {
    const float* x      = (const float*)d_in[0];  // [64,256,56,56]
    const float* embeds = (const float*)d_in[1];  // [64,16]
    const float* table  = (const float*)d_in[2];  // [16,256]
    float* out = (float*)d_out;

    mask_kernel<<<NN, CC>>>(embeds, table);
    scale_kernel<<<NN * CC, 256>>>((const float4*)x, (float4*)out);
}

// round 2
// speedup vs baseline: 1.0635x; 1.0635x over previous
#include <cuda_runtime.h>

// Problem constants (from reference)
#define NN 64
#define CC 256
#define HH 56
#define WW 56
#define EMBED 16
#define INDEX_K 16              // ceil(256^0.5) = 16
#define HW (HH * WW)            // 3136
#define HW4 (HW / 4)            // 784 float4 per (n,c) slab
#define SCALE (256.0f / 240.0f) // c / (c - INDEX)

// Fused kernel: one block per (n,c) slab.
//  - Issue the slab's float4 DRAM loads first (long-latency, MLP=3..4).
//  - While those are in flight, compute activ[n][:] cooperatively
//    (thread j -> channel j), rank via __syncthreads_count.
//  - Multiply the loaded registers by keep*scale and store.
__global__ void __launch_bounds__(256) fused_kernel(const float4* __restrict__ x,
                                                    const float* __restrict__ embeds,
                                                    const float* __restrict__ table,
                                                    float4* __restrict__ out) {
    __shared__ float s_act[CC];

    const int nc = blockIdx.x;
    const int n = nc >> 8;       // sample
    const int c = nc & 255;      // channel this block scales
    const int t = threadIdx.x;

    const long long base = (long long)nc * HW4;
    const float4* __restrict__ xin = x + base;
    float4* __restrict__ o = out + base;

    // ---- issue DRAM loads up front (streaming: bypass L2 retention) ----
    const bool tail = (t < (HW4 - 3 * 256));   // 784 = 3*256 + 16
    float4 v0 = __ldcs(xin + t);
    float4 v1 = __ldcs(xin + t + 256);
    float4 v2 = __ldcs(xin + t + 512);
    float4 v3;
    if (tail) v3 = __ldcs(xin + t + 768);

    // ---- mask computation overlapped with the loads above ----
    // activ[n][t] = sum_e embeds[n][e] * table[e][t]
    float a = 0.0f;
#pragma unroll
    for (int e = 0; e < EMBED; ++e) {
        a += __ldg(embeds + n * EMBED + e) * __ldg(table + e * CC + t);
    }
    s_act[t] = a;
    __syncthreads();
    const float ac = s_act[c];
    // keep <=> #{j : activ[j] <= activ[c]} >= INDEX_K+1  (tie-safe, == sorted[16] <= activ[c])
    const int cnt = __syncthreads_count(a <= ac);
    const float m = (cnt >= INDEX_K + 1) ? SCALE : 0.0f;

    // ---- scale + store (streaming) ----
    v0.x *= m; v0.y *= m; v0.z *= m; v0.w *= m;
    v1.x *= m; v1.y *= m; v1.z *= m; v1.w *= m;
    v2.x *= m; v2.y *= m; v2.z *= m; v2.w *= m;
    __stcs(o + t, v0);
    __stcs(o + t + 256, v1);
    __stcs(o + t + 512, v2);
    if (tail) {
        v3.x *= m; v3.y *= m; v3.z *= m; v3.w *= m;
        __stcs(o + t + 768, v3);
    }
}

extern "C" void kernel_launch(void* const* d_in, const int* in_sizes, int n_in,
                              void* d_out, int out_size) {
    const float* x      = (const float*)d_in[0];  // [64,256,56,56]
    const float* embeds = (const float*)d_in[1];  // [64,16]
    const float* table  = (const float*)d_in[2];  // [16,256]
    float* out = (float*)d_out;

    fused_kernel<<<NN * CC, 256>>>((const float4*)x, embeds, table, (float4*)out);
}